// round 12
// baseline (speedup 1.0000x reference)
#include <cuda_runtime.h>
#include <math.h>
#include <stdint.h>

// ---------------------------------------------------------------------------
// GWEModel: tokens -> embed -> 8x[rmsnorm, x+=0.1*(h@W.T), rmsnorm,
//           x+=0.1*silu(h@Wffn.T)] -> rmsnorm -> lm_head
// All GEMMs are NT-SGEMMs using Blackwell packed fma.rn.f32x2 (FFMA2):
// 2 fp32 MACs per issued instruction, exact fp32 arithmetic.
// ---------------------------------------------------------------------------

#define D       1024
#define NLAYERS 8
#define VOCAB   32000
#define BSZ     16
#define GH      256
#define NFREQS  6
#define NTOK    4096
#define NB      64
#define NMAT    16
#define NROWS   (NMAT * NB * NB)   // 65536 generator rows
#define ENC_K   64                 // 52 features padded to 64
#define EPSV    1.1920929e-07f

// ------------------------- scratch (device globals) ------------------------
__device__ float g_X[NTOK * D];
__device__ float g_H[NTOK * D];
__device__ float g_W[(size_t)NMAT * D * D];
__device__ float g_G0[(size_t)NROWS * GH];
__device__ float g_G1[(size_t)NROWS * GH];
__device__ float g_ENC[(size_t)NROWS * ENC_K];
__device__ float g_W0P[GH * ENC_K];

// ------------------------------ tiny kernels -------------------------------
__global__ void k_gather(const int* __restrict__ tok,
                         const float* __restrict__ emb) {
    int t  = blockIdx.x;
    int tk = tok[t];
    const float4* src = (const float4*)(emb + (size_t)tk * D);
    float4*       dst = (float4*)(g_X + (size_t)t * D);
    dst[threadIdx.x] = src[threadIdx.x];
}

__global__ void k_padw0(const float* __restrict__ w0) {
    int g = blockIdx.x;
    int f = threadIdx.x;
    g_W0P[g * ENC_K + f] = (f < 52) ? w0[g * 52 + f] : 0.0f;
}

__global__ void k_encode() {
    int idx = blockIdx.x * blockDim.x + threadIdx.x;
    if (idx >= NROWS * ENC_K) return;
    int row = idx >> 6;
    int f   = idx & 63;
    float val = 0.0f;
    if (f < 52) {
        int   mat = row >> 12;
        int   blk = row & 4095;
        float c0  = (float)(mat >> 1) * (1.0f / 7.0f);
        float c1  = (float)(blk >> 6) * (1.0f / 63.0f);
        float c2  = (float)(blk & 63) * (1.0f / 63.0f);
        float c3  = (mat & 1) ? 0.5f : 0.0f;
        float coords[4] = {c0, c1, c2, c3};
        if (f < 4) {
            val = coords[f];
        } else {
            int   q = f - 4;
            int   g = q >> 3;
            int   r = q & 7;
            float a = (float)(1 << g) * 3.14159265358979f * coords[r & 3];
            val = (r >= 4) ? cosf(a) : sinf(a);
        }
    }
    g_ENC[idx] = val;
}

__global__ void k_rmsnorm(const float* __restrict__ x,
                          const float* __restrict__ w,
                          float* __restrict__ h) {
    int t   = threadIdx.x;
    int row = blockIdx.x;
    const float4* xr = (const float4*)(x + (size_t)row * D);
    float4 a = xr[t];
    float  s = a.x * a.x + a.y * a.y + a.z * a.z + a.w * a.w;
    #pragma unroll
    for (int o = 16; o > 0; o >>= 1) s += __shfl_xor_sync(0xffffffffu, s, o);
    __shared__ float sm[8];
    if ((t & 31) == 0) sm[t >> 5] = s;
    __syncthreads();
    float tot = 0.0f;
    #pragma unroll
    for (int i = 0; i < 8; i++) tot += sm[i];
    float inv = rsqrtf(tot * (1.0f / 1024.0f) + EPSV);
    float4 wv = ((const float4*)w)[t];
    float4 o;
    o.x = a.x * inv * wv.x; o.y = a.y * inv * wv.y;
    o.z = a.z * inv * wv.z; o.w = a.w * inv * wv.w;
    ((float4*)(h + (size_t)row * D))[t] = o;
}

// ------------------------------ SGEMM (NT, FFMA2) ---------------------------
// C[M,N] = A[M,K] @ B[N,K]^T, 128x128 tile, BK=16, 256 threads, 8x8/thread.
// Accumulators are packed f32x2 pairs along N: 32 fma.rn.f32x2 per k-step.
enum { EPI_STORE = 0, EPI_SILU = 1, EPI_GENW = 2, EPI_RESID = 3, EPI_RESID_SILU = 4 };

__device__ __forceinline__ float siluf(float v) {
    return v / (1.0f + __expf(-v));
}

template <int EPI>
__global__ __launch_bounds__(256)
void k_sgemm(const float* __restrict__ A, const float* __restrict__ B,
             const float* __restrict__ bias, float* __restrict__ OUT,
             int M, int N, int K) {
    __shared__ float As[16][128];
    __shared__ float Bs[16][128];
    const int tid = threadIdx.x;
    const int tx  = tid & 15;      // 0..15 -> N
    const int ty  = tid >> 4;      // 0..15 -> M
    const int bm  = blockIdx.y * 128;
    const int bn  = blockIdx.x * 128;
    const float* Ab = A + (size_t)bm * K;
    const float* Bb = B + (size_t)bn * K;

    unsigned long long acc[8][4];
    #pragma unroll
    for (int i = 0; i < 8; i++)
        #pragma unroll
        for (int j = 0; j < 4; j++) acc[i][j] = 0ull;

    for (int k0 = 0; k0 < K; k0 += 16) {
        #pragma unroll
        for (int it = 0; it < 2; it++) {
            int idx = tid + it * 256;
            int r   = idx >> 2;            // 0..127 tile row
            int c   = (idx & 3) << 2;      // 0,4,8,12 k-offset
            float4 va = *(const float4*)(Ab + (size_t)r * K + k0 + c);
            As[c + 0][r] = va.x; As[c + 1][r] = va.y;
            As[c + 2][r] = va.z; As[c + 3][r] = va.w;
            float4 vb = *(const float4*)(Bb + (size_t)r * K + k0 + c);
            Bs[c + 0][r] = vb.x; Bs[c + 1][r] = vb.y;
            Bs[c + 2][r] = vb.z; Bs[c + 3][r] = vb.w;
        }
        __syncthreads();
        #pragma unroll
        for (int k = 0; k < 16; k++) {
            float ra[8];
            *(float4*)(ra)     = *(const float4*)&As[k][ty * 8];
            *(float4*)(ra + 4) = *(const float4*)&As[k][ty * 8 + 4];
            unsigned long long rb[4];
            {
                ulonglong2 t0 = *(const ulonglong2*)&Bs[k][tx * 8];
                ulonglong2 t1 = *(const ulonglong2*)&Bs[k][tx * 8 + 4];
                rb[0] = t0.x; rb[1] = t0.y; rb[2] = t1.x; rb[3] = t1.y;
            }
            #pragma unroll
            for (int i = 0; i < 8; i++) {
                unsigned long long aa;
                asm("mov.b64 %0, {%1, %1};" : "=l"(aa) : "f"(ra[i]));
                #pragma unroll
                for (int j = 0; j < 4; j++) {
                    asm("fma.rn.f32x2 %0, %1, %2, %0;"
                        : "+l"(acc[i][j]) : "l"(aa), "l"(rb[j]));
                }
            }
        }
        __syncthreads();
    }

    // ------------------------------ epilogue --------------------------------
    #pragma unroll
    for (int i = 0; i < 8; i++) {
        int m = bm + ty * 8 + i;
        #pragma unroll
        for (int j = 0; j < 4; j++) {
            float vlo, vhi;
            asm("mov.b64 {%0, %1}, %2;" : "=f"(vlo), "=f"(vhi) : "l"(acc[i][j]));
            int n0 = bn + tx * 8 + 2 * j;       // even; pair is contiguous
            if (EPI == EPI_STORE) {
                *(float2*)&OUT[(size_t)m * N + n0] = make_float2(vlo, vhi);
            } else if (EPI == EPI_SILU) {
                float2 bb = *(const float2*)&bias[n0];
                *(float2*)&OUT[(size_t)m * N + n0] =
                    make_float2(siluf(vlo + bb.x), siluf(vhi + bb.y));
            } else if (EPI == EPI_GENW) {
                float2 bb = *(const float2*)&bias[n0];
                int mat = m >> 12;
                int rb_ = (m >> 6) & 63;
                int cb_ = m & 63;
                int ii  = n0 >> 4;
                int jj  = n0 & 15;  // even; jj+1 stays inside the 16-block
                float2* dst = (float2*)&g_W[(size_t)mat * (D * D)
                    + (size_t)(rb_ * 16 + ii) * D + (cb_ * 16 + jj)];
                *dst = make_float2(vlo + bb.x, vhi + bb.y);
            } else if (EPI == EPI_RESID) {
                float2* dst = (float2*)&OUT[(size_t)m * N + n0];
                float2 cur = *dst;
                *dst = make_float2(cur.x + 0.1f * vlo, cur.y + 0.1f * vhi);
            } else { // EPI_RESID_SILU
                float2* dst = (float2*)&OUT[(size_t)m * N + n0];
                float2 cur = *dst;
                *dst = make_float2(cur.x + 0.1f * siluf(vlo),
                                   cur.y + 0.1f * siluf(vhi));
            }
        }
    }
}

// --------------------------------- driver -----------------------------------
extern "C" void kernel_launch(void* const* d_in, const int* in_sizes, int n_in,
                              void* d_out, int out_size) {
    const int*   tokens = (const int*)d_in[0];
    const float* embed  = (const float*)d_in[1];
    const float* lmhead = (const float*)d_in[2];
    const float* finw   = (const float*)d_in[3];
    const float* n1w    = (const float*)d_in[4];
    const float* n2w    = (const float*)d_in[5];
    const float* w0     = (const float*)d_in[6];
    const float* b0     = (const float*)d_in[7];
    const float* w1     = (const float*)d_in[8];
    const float* b1     = (const float*)d_in[9];
    const float* w2     = (const float*)d_in[10];
    const float* b2     = (const float*)d_in[11];
    const float* w3     = (const float*)d_in[12];
    const float* b3     = (const float*)d_in[13];
    float* out = (float*)d_out;

    float *pX, *pH, *pW, *pG0, *pG1, *pENC, *pW0P;
    cudaGetSymbolAddress((void**)&pX,   g_X);
    cudaGetSymbolAddress((void**)&pH,   g_H);
    cudaGetSymbolAddress((void**)&pW,   g_W);
    cudaGetSymbolAddress((void**)&pG0,  g_G0);
    cudaGetSymbolAddress((void**)&pG1,  g_G1);
    cudaGetSymbolAddress((void**)&pENC, g_ENC);
    cudaGetSymbolAddress((void**)&pW0P, g_W0P);

    // --- embed gather + generator input encoding ---
    k_gather<<<NTOK, 256>>>(tokens, embed);
    k_padw0<<<GH, ENC_K>>>(w0);
    k_encode<<<(NROWS * ENC_K + 255) / 256, 256>>>();

    // --- generate all 16 weight matrices in one batched MLP pass ---
    dim3 gg(GH / 128, NROWS / 128);   // (2, 512)
    k_sgemm<EPI_SILU><<<gg, 256>>>(pENC, pW0P, b0, pG0, NROWS, GH, ENC_K);
    k_sgemm<EPI_SILU><<<gg, 256>>>(pG0,  w1,   b1, pG1, NROWS, GH, GH);
    k_sgemm<EPI_SILU><<<gg, 256>>>(pG1,  w2,   b2, pG0, NROWS, GH, GH);
    k_sgemm<EPI_GENW><<<gg, 256>>>(pG0,  w3,   b3, pW,  NROWS, GH, GH);

    // --- 8 transformer layers ---
    dim3 gl(D / 128, NTOK / 128);     // (8, 32)
    for (int li = 0; li < NLAYERS; li++) {
        k_rmsnorm<<<NTOK, 256>>>(pX, n1w + (size_t)li * D, pH);
        k_sgemm<EPI_RESID><<<gl, 256>>>(
            pH, pW + (size_t)(2 * li) * D * D, nullptr, pX, NTOK, D, D);
        k_rmsnorm<<<NTOK, 256>>>(pX, n2w + (size_t)li * D, pH);
        k_sgemm<EPI_RESID_SILU><<<gl, 256>>>(
            pH, pW + (size_t)(2 * li + 1) * D * D, nullptr, pX, NTOK, D, D);
    }

    // --- final norm + LM head ---
    k_rmsnorm<<<NTOK, 256>>>(pX, finw, pH);
    dim3 gf(VOCAB / 128, NTOK / 128); // (250, 32)
    k_sgemm<EPI_STORE><<<gf, 256>>>(pH, lmhead, nullptr, out, NTOK, VOCAB, D);
}

// round 14
// speedup vs baseline: 2.2538x; 2.2538x over previous
#include <cuda_runtime.h>
#include <cuda_bf16.h>
#include <math.h>
#include <stdint.h>

// ---------------------------------------------------------------------------
// GWEModel on tensor cores via baseline warp-MMA (HMMA, PTX mma.sync m16n8k16).
// Every GEMM is C[M,N] = A[M,K] @ B[N,K]^T computed as split-bf16 fp32
// emulation: A = Ahi+Alo, B = Bhi+Blo (bf16), C = Ahi*Bhi + Ahi*Blo + Alo*Bhi
// accumulated in fp32.  CTA tile 128x128, BK=32, cp.async double buffering.
// ---------------------------------------------------------------------------

#define D       1024
#define NLAYERS 8
#define VOCAB   32000
#define GH      256
#define NTOK    4096
#define NMAT    16
#define NROWS   65536
#define ENC_K   64
#define EPSV    1.1920929e-07f

typedef __nv_bfloat16 bf16;

// ------------------------- scratch (device globals) ------------------------
__device__ float g_Xf[NTOK * D];                                   // fp32 residual
__device__ bf16  g_Hhi[NTOK * D],  g_Hlo[NTOK * D];                // normed acts
__device__ bf16  g_Whi[(size_t)NMAT * D * D], g_Wlo[(size_t)NMAT * D * D];
__device__ bf16  g_G0hi[(size_t)NROWS * GH], g_G0lo[(size_t)NROWS * GH];
__device__ bf16  g_G1hi[(size_t)NROWS * GH], g_G1lo[(size_t)NROWS * GH];
__device__ bf16  g_Ehi[(size_t)NROWS * ENC_K], g_Elo[(size_t)NROWS * ENC_K];
__device__ bf16  g_W0Phi[GH * ENC_K], g_W0Plo[GH * ENC_K];
__device__ bf16  g_W1hi[GH * GH], g_W1lo[GH * GH];
__device__ bf16  g_W2hi[GH * GH], g_W2lo[GH * GH];
__device__ bf16  g_W3hi[GH * GH], g_W3lo[GH * GH];
__device__ bf16  g_LMhi[(size_t)VOCAB * D], g_LMlo[(size_t)VOCAB * D];

// ------------------------------- PTX helpers -------------------------------
__device__ __forceinline__ uint32_t smem_u32(const void* p) {
    uint32_t a;
    asm("{ .reg .u64 t; cvta.to.shared.u64 t, %1; cvt.u32.u64 %0, t; }"
        : "=r"(a) : "l"(p));
    return a;
}

__device__ __forceinline__ void ldmx4(uint32_t* r, uint32_t addr) {
    asm volatile("ldmatrix.sync.aligned.m8n8.x4.shared.b16 {%0,%1,%2,%3}, [%4];"
                 : "=r"(r[0]), "=r"(r[1]), "=r"(r[2]), "=r"(r[3]) : "r"(addr));
}

__device__ __forceinline__ void mma16816(float* c, const uint32_t* a,
                                         uint32_t b0, uint32_t b1) {
    asm volatile(
        "mma.sync.aligned.m16n8k16.row.col.f32.bf16.bf16.f32 "
        "{%0,%1,%2,%3}, {%4,%5,%6,%7}, {%8,%9}, {%0,%1,%2,%3};"
        : "+f"(c[0]), "+f"(c[1]), "+f"(c[2]), "+f"(c[3])
        : "r"(a[0]), "r"(a[1]), "r"(a[2]), "r"(a[3]), "r"(b0), "r"(b1));
}

__device__ __forceinline__ void cp16(uint32_t saddr, const void* gaddr) {
    asm volatile("cp.async.cg.shared.global [%0], [%1], 16;"
                 :: "r"(saddr), "l"(gaddr) : "memory");
}
#define CP_COMMIT() asm volatile("cp.async.commit_group;" ::: "memory")
#define CP_WAIT(N)  asm volatile("cp.async.wait_group %0;" :: "n"(N) : "memory")

// --------------------------- split/misc helpers ----------------------------
__device__ __forceinline__ void split1(float v, bf16& h, bf16& l) {
    h = __float2bfloat16(v);
    l = __float2bfloat16(v - __bfloat162float(h));
}

__device__ __forceinline__ void store_split2(bf16* ph, bf16* pl,
                                             float v0, float v1) {
    bf16 h0, l0, h1, l1;
    split1(v0, h0, l0); split1(v1, h1, l1);
    __nv_bfloat162 hh; hh.x = h0; hh.y = h1;
    __nv_bfloat162 ll; ll.x = l0; ll.y = l1;
    *(__nv_bfloat162*)ph = hh;
    *(__nv_bfloat162*)pl = ll;
}

__device__ __forceinline__ void store_split4(bf16* ph, bf16* pl,
                                             float v0, float v1, float v2, float v3) {
    store_split2(ph, pl, v0, v1);
    store_split2(ph + 2, pl + 2, v2, v3);
}

__device__ __forceinline__ float siluf(float v) {
    return v / (1.0f + __expf(-v));
}

// ------------------------------ tiny kernels -------------------------------
__global__ void k_gather(const int* __restrict__ tok,
                         const float* __restrict__ emb) {
    int t  = blockIdx.x;
    int tk = tok[t];
    const float4* src = (const float4*)(emb + (size_t)tk * D);
    float4*       dst = (float4*)(g_Xf + (size_t)t * D);
    dst[threadIdx.x] = src[threadIdx.x];
}

__global__ void k_padw0(const float* __restrict__ w0) {
    int g = blockIdx.x;
    int f = threadIdx.x;
    float v = (f < 52) ? w0[g * 52 + f] : 0.0f;
    bf16 h, l; split1(v, h, l);
    g_W0Phi[g * ENC_K + f] = h;
    g_W0Plo[g * ENC_K + f] = l;
}

__global__ void k_split(const float* __restrict__ s, bf16* __restrict__ hi,
                        bf16* __restrict__ lo, int n) {
    int i = blockIdx.x * blockDim.x + threadIdx.x;
    if (i < n) {
        bf16 h, l; split1(s[i], h, l);
        hi[i] = h; lo[i] = l;
    }
}

__global__ void k_encode() {
    int idx = blockIdx.x * blockDim.x + threadIdx.x;
    if (idx >= NROWS * ENC_K) return;
    int row = idx >> 6;
    int f   = idx & 63;
    float val = 0.0f;
    if (f < 52) {
        int   mat = row >> 12;
        int   blk = row & 4095;
        float c0  = (float)(mat >> 1) * (1.0f / 7.0f);
        float c1  = (float)(blk >> 6) * (1.0f / 63.0f);
        float c2  = (float)(blk & 63) * (1.0f / 63.0f);
        float c3  = (mat & 1) ? 0.5f : 0.0f;
        float coords[4] = {c0, c1, c2, c3};
        if (f < 4) {
            val = coords[f];
        } else {
            int   q = f - 4;
            int   g = q >> 3;
            int   r = q & 7;
            float a = (float)(1 << g) * 3.14159265358979f * coords[r & 3];
            val = (r >= 4) ? cosf(a) : sinf(a);
        }
    }
    bf16 h, l; split1(val, h, l);
    g_Ehi[idx] = h; g_Elo[idx] = l;
}

__global__ void k_rmsnorm(const float* __restrict__ x,
                          const float* __restrict__ w,
                          bf16* __restrict__ hhi, bf16* __restrict__ hlo) {
    int t   = threadIdx.x;   // 256
    int row = blockIdx.x;
    const float4* xr = (const float4*)(x + (size_t)row * D);
    float4 a = xr[t];
    float  s = a.x * a.x + a.y * a.y + a.z * a.z + a.w * a.w;
    #pragma unroll
    for (int o = 16; o > 0; o >>= 1) s += __shfl_xor_sync(0xffffffffu, s, o);
    __shared__ float sm[8];
    if ((t & 31) == 0) sm[t >> 5] = s;
    __syncthreads();
    float tot = 0.0f;
    #pragma unroll
    for (int i = 0; i < 8; i++) tot += sm[i];
    float inv = rsqrtf(tot * (1.0f / 1024.0f) + EPSV);
    float4 wv = ((const float4*)w)[t];
    store_split4(hhi + (size_t)row * D + t * 4, hlo + (size_t)row * D + t * 4,
                 a.x * inv * wv.x, a.y * inv * wv.y,
                 a.z * inv * wv.z, a.w * inv * wv.w);
}

// ------------------------- HMMA split-bf16 GEMM ------------------------------
// grid.x = M/128 (fast axis -> B-tile reuse in L2), grid.y = N/128.
// 256 threads = 8 warps in 2(M) x 4(N); warp tile 64x32; BK=32, 2 stages.
// SMEM per stage: Ahi|Alo|Bhi|Blo, each 128 rows x 40 bf16 (80B stride).
enum { EPI_STORE = 0, EPI_SILU = 1, EPI_GENW = 2, EPI_RESID = 3, EPI_RESID_SILU = 4 };

#define LDB        80            // row stride in bytes (32 bf16 + 8 pad)
#define MAT_BYTES  10240         // 128 * 80
#define STAGE      40960         // 4 matrices
#define GEMM_SMEM  (2 * STAGE)

template <int EPI>
__global__ void __launch_bounds__(256)
k_gemm(const bf16* __restrict__ Ahi, const bf16* __restrict__ Alo,
       const bf16* __restrict__ Bhi, const bf16* __restrict__ Blo,
       const float* __restrict__ bias,
       float* __restrict__ outF,
       bf16* __restrict__ outHi, bf16* __restrict__ outLo,
       int M, int N, int K) {
    extern __shared__ char smem[];
    const uint32_t sb   = smem_u32(smem);
    const int tid  = threadIdx.x;
    const int lane = tid & 31;
    const int wid  = tid >> 5;
    const int wm   = wid >> 2;          // 0..1
    const int wn   = wid & 3;           // 0..3
    const int bm   = blockIdx.x * 128;
    const int bn   = blockIdx.y * 128;

    float acc[4][4][4];
    #pragma unroll
    for (int i = 0; i < 4; i++)
        #pragma unroll
        for (int j = 0; j < 4; j++)
            #pragma unroll
            for (int q = 0; q < 4; q++) acc[i][j][q] = 0.0f;

    // ldmatrix per-lane byte offsets
    const uint32_t a_off = (uint32_t)(lane & 15) * LDB + (uint32_t)(lane >> 4) * 16;
    const uint32_t b_off = (uint32_t)((lane & 7) + ((lane >> 4) & 1) * 8) * LDB
                         + (uint32_t)((lane >> 3) & 1) * 16;

    const int nch = K >> 5;

    // ---- stage loader: 2048 x 16B cp.async ----
    auto load_stage = [&](int ic, int buf) {
        const int k0 = ic << 5;
        const uint32_t sbase = sb + buf * STAGE;
        #pragma unroll
        for (int it = 0; it < 8; it++) {
            int u   = tid + it * 256;
            int seg = u >> 2;
            int c   = u & 3;
            const bf16* src; uint32_t moff; int rl;
            if (seg < 128)      { src = Ahi + (size_t)(bm + seg) * K;       moff = 0;            rl = seg; }
            else if (seg < 256) { src = Alo + (size_t)(bm + seg - 128) * K; moff = MAT_BYTES;     rl = seg - 128; }
            else if (seg < 384) { src = Bhi + (size_t)(bn + seg - 256) * K; moff = 2 * MAT_BYTES; rl = seg - 256; }
            else                { src = Blo + (size_t)(bn + seg - 384) * K; moff = 3 * MAT_BYTES; rl = seg - 384; }
            cp16(sbase + moff + (uint32_t)rl * LDB + (uint32_t)c * 16, src + k0 + c * 8);
        }
        CP_COMMIT();
    };

    auto compute = [&](int buf) {
        const uint32_t base = sb + buf * STAGE;
        #pragma unroll
        for (int ks = 0; ks < 2; ks++) {
            uint32_t ah[4][4], al[4][4], bh[2][4], bl[2][4];
            #pragma unroll
            for (int mt = 0; mt < 4; mt++) {
                uint32_t t0 = (uint32_t)(wm * 64 + mt * 16) * LDB + (uint32_t)ks * 32;
                ldmx4(ah[mt], base + t0 + a_off);
                ldmx4(al[mt], base + MAT_BYTES + t0 + a_off);
            }
            #pragma unroll
            for (int g = 0; g < 2; g++) {
                uint32_t t0 = (uint32_t)(wn * 32 + g * 16) * LDB + (uint32_t)ks * 32;
                ldmx4(bh[g], base + 2 * MAT_BYTES + t0 + b_off);
                ldmx4(bl[g], base + 3 * MAT_BYTES + t0 + b_off);
            }
            #pragma unroll
            for (int mt = 0; mt < 4; mt++)
                #pragma unroll
                for (int nt = 0; nt < 4; nt++) {
                    const int g = nt >> 1, h = (nt & 1) * 2;
                    mma16816(acc[mt][nt], ah[mt], bh[g][h], bh[g][h + 1]);
                    mma16816(acc[mt][nt], ah[mt], bl[g][h], bl[g][h + 1]);
                    mma16816(acc[mt][nt], al[mt], bh[g][h], bh[g][h + 1]);
                }
        }
    };

    // ---- pipelined main loop ----
    load_stage(0, 0);
    if (nch > 1) load_stage(1, 1);
    for (int ic = 0; ic < nch; ic++) {
        if (ic + 1 < nch) { CP_WAIT(1); } else { CP_WAIT(0); }
        __syncthreads();
        compute(ic & 1);
        __syncthreads();
        if (ic + 2 < nch) load_stage(ic + 2, ic & 1);
    }

    // ------------------------------ epilogue --------------------------------
    #pragma unroll
    for (int mt = 0; mt < 4; mt++) {
        #pragma unroll
        for (int nt = 0; nt < 4; nt++) {
            const int n0 = bn + wn * 32 + nt * 8 + (lane & 3) * 2;
            #pragma unroll
            for (int half = 0; half < 2; half++) {
                const int m = bm + wm * 64 + mt * 16 + (lane >> 2) + half * 8;
                float v0 = acc[mt][nt][half * 2 + 0];
                float v1 = acc[mt][nt][half * 2 + 1];
                if (EPI == EPI_STORE) {
                    *(float2*)&outF[(size_t)m * N + n0] = make_float2(v0, v1);
                } else if (EPI == EPI_SILU) {
                    const float2 bb = *(const float2*)&bias[n0];
                    store_split2(outHi + (size_t)m * N + n0,
                                 outLo + (size_t)m * N + n0,
                                 siluf(v0 + bb.x), siluf(v1 + bb.y));
                } else if (EPI == EPI_GENW) {
                    const float2 bb = *(const float2*)&bias[n0];
                    int mat = m >> 12, rb_ = (m >> 6) & 63, cb_ = m & 63;
                    int ii = n0 >> 4, jj = n0 & 15;  // pair stays in 16-block
                    size_t off = (size_t)mat * D * D + (size_t)(rb_ * 16 + ii) * D
                               + (size_t)(cb_ * 16 + jj);
                    store_split2(outHi + off, outLo + off, v0 + bb.x, v1 + bb.y);
                } else if (EPI == EPI_RESID) {
                    float2* p = (float2*)&outF[(size_t)m * N + n0];
                    float2 c = *p;
                    *p = make_float2(c.x + 0.1f * v0, c.y + 0.1f * v1);
                } else { // EPI_RESID_SILU
                    float2* p = (float2*)&outF[(size_t)m * N + n0];
                    float2 c = *p;
                    *p = make_float2(c.x + 0.1f * siluf(v0), c.y + 0.1f * siluf(v1));
                }
            }
        }
    }
}

// --------------------------------- driver -----------------------------------
extern "C" void kernel_launch(void* const* d_in, const int* in_sizes, int n_in,
                              void* d_out, int out_size) {
    const int*   tokens = (const int*)d_in[0];
    const float* embed  = (const float*)d_in[1];
    const float* lmhead = (const float*)d_in[2];
    const float* finw   = (const float*)d_in[3];
    const float* n1w    = (const float*)d_in[4];
    const float* n2w    = (const float*)d_in[5];
    const float* w0     = (const float*)d_in[6];
    const float* b0     = (const float*)d_in[7];
    const float* w1     = (const float*)d_in[8];
    const float* b1     = (const float*)d_in[9];
    const float* w2     = (const float*)d_in[10];
    const float* b2     = (const float*)d_in[11];
    const float* w3     = (const float*)d_in[12];
    const float* b3     = (const float*)d_in[13];
    float* out = (float*)d_out;

    float *pXf;
    bf16 *pHhi, *pHlo, *pWhi, *pWlo, *pG0hi, *pG0lo, *pG1hi, *pG1lo;
    bf16 *pEhi, *pElo, *pW0Phi, *pW0Plo;
    bf16 *pW1hi, *pW1lo, *pW2hi, *pW2lo, *pW3hi, *pW3lo, *pLMhi, *pLMlo;
    cudaGetSymbolAddress((void**)&pXf,    g_Xf);
    cudaGetSymbolAddress((void**)&pHhi,   g_Hhi);
    cudaGetSymbolAddress((void**)&pHlo,   g_Hlo);
    cudaGetSymbolAddress((void**)&pWhi,   g_Whi);
    cudaGetSymbolAddress((void**)&pWlo,   g_Wlo);
    cudaGetSymbolAddress((void**)&pG0hi,  g_G0hi);
    cudaGetSymbolAddress((void**)&pG0lo,  g_G0lo);
    cudaGetSymbolAddress((void**)&pG1hi,  g_G1hi);
    cudaGetSymbolAddress((void**)&pG1lo,  g_G1lo);
    cudaGetSymbolAddress((void**)&pEhi,   g_Ehi);
    cudaGetSymbolAddress((void**)&pElo,   g_Elo);
    cudaGetSymbolAddress((void**)&pW0Phi, g_W0Phi);
    cudaGetSymbolAddress((void**)&pW0Plo, g_W0Plo);
    cudaGetSymbolAddress((void**)&pW1hi,  g_W1hi);
    cudaGetSymbolAddress((void**)&pW1lo,  g_W1lo);
    cudaGetSymbolAddress((void**)&pW2hi,  g_W2hi);
    cudaGetSymbolAddress((void**)&pW2lo,  g_W2lo);
    cudaGetSymbolAddress((void**)&pW3hi,  g_W3hi);
    cudaGetSymbolAddress((void**)&pW3lo,  g_W3lo);
    cudaGetSymbolAddress((void**)&pLMhi,  g_LMhi);
    cudaGetSymbolAddress((void**)&pLMlo,  g_LMlo);

    cudaFuncSetAttribute(k_gemm<EPI_STORE>,      cudaFuncAttributeMaxDynamicSharedMemorySize, GEMM_SMEM);
    cudaFuncSetAttribute(k_gemm<EPI_SILU>,       cudaFuncAttributeMaxDynamicSharedMemorySize, GEMM_SMEM);
    cudaFuncSetAttribute(k_gemm<EPI_GENW>,       cudaFuncAttributeMaxDynamicSharedMemorySize, GEMM_SMEM);
    cudaFuncSetAttribute(k_gemm<EPI_RESID>,      cudaFuncAttributeMaxDynamicSharedMemorySize, GEMM_SMEM);
    cudaFuncSetAttribute(k_gemm<EPI_RESID_SILU>, cudaFuncAttributeMaxDynamicSharedMemorySize, GEMM_SMEM);

    // --- inputs -> bf16 splits, embed gather, coord encoding ---
    k_gather<<<NTOK, 256>>>(tokens, embed);
    k_padw0<<<GH, ENC_K>>>(w0);
    k_encode<<<(NROWS * ENC_K + 255) / 256, 256>>>();
    k_split<<<(GH * GH + 255) / 256, 256>>>(w1, pW1hi, pW1lo, GH * GH);
    k_split<<<(GH * GH + 255) / 256, 256>>>(w2, pW2hi, pW2lo, GH * GH);
    k_split<<<(GH * GH + 255) / 256, 256>>>(w3, pW3hi, pW3lo, GH * GH);
    k_split<<<(VOCAB * D + 255) / 256, 256>>>(lmhead, pLMhi, pLMlo, VOCAB * D);

    // --- generate all 16 weight matrices (batched coord-MLP) ---
    dim3 gg(NROWS / 128, GH / 128);   // (512, 2)
    k_gemm<EPI_SILU><<<gg, 256, GEMM_SMEM>>>(pEhi, pElo, pW0Phi, pW0Plo, b0,
                                             nullptr, pG0hi, pG0lo, NROWS, GH, ENC_K);
    k_gemm<EPI_SILU><<<gg, 256, GEMM_SMEM>>>(pG0hi, pG0lo, pW1hi, pW1lo, b1,
                                             nullptr, pG1hi, pG1lo, NROWS, GH, GH);
    k_gemm<EPI_SILU><<<gg, 256, GEMM_SMEM>>>(pG1hi, pG1lo, pW2hi, pW2lo, b2,
                                             nullptr, pG0hi, pG0lo, NROWS, GH, GH);
    k_gemm<EPI_GENW><<<gg, 256, GEMM_SMEM>>>(pG0hi, pG0lo, pW3hi, pW3lo, b3,
                                             nullptr, pWhi, pWlo, NROWS, GH, GH);

    // --- 8 transformer layers ---
    dim3 gl(NTOK / 128, D / 128);     // (32, 8)
    for (int li = 0; li < NLAYERS; li++) {
        k_rmsnorm<<<NTOK, 256>>>(pXf, n1w + (size_t)li * D, pHhi, pHlo);
        k_gemm<EPI_RESID><<<gl, 256, GEMM_SMEM>>>(
            pHhi, pHlo, pWhi + (size_t)(2 * li) * D * D,
            pWlo + (size_t)(2 * li) * D * D, nullptr,
            pXf, nullptr, nullptr, NTOK, D, D);
        k_rmsnorm<<<NTOK, 256>>>(pXf, n2w + (size_t)li * D, pHhi, pHlo);
        k_gemm<EPI_RESID_SILU><<<gl, 256, GEMM_SMEM>>>(
            pHhi, pHlo, pWhi + (size_t)(2 * li + 1) * D * D,
            pWlo + (size_t)(2 * li + 1) * D * D, nullptr,
            pXf, nullptr, nullptr, NTOK, D, D);
    }

    // --- final norm + LM head ---
    k_rmsnorm<<<NTOK, 256>>>(pXf, finw, pHhi, pHlo);
    dim3 gf(NTOK / 128, VOCAB / 128); // (32, 250)
    k_gemm<EPI_STORE><<<gf, 256, GEMM_SMEM>>>(
        pHhi, pHlo, pLMhi, pLMlo, nullptr, out, nullptr, nullptr,
        NTOK, VOCAB, D);
}

// round 15
// speedup vs baseline: 3.3856x; 1.5021x over previous
#include <cuda_runtime.h>
#include <cuda_fp16.h>
#include <math.h>
#include <stdint.h>

// ---------------------------------------------------------------------------
// GWEModel on tensor cores via baseline warp-MMA (HMMA, mma.sync m16n8k16 fp16).
// GEMMs are C[M,N] = A[M,K] @ B[N,K]^T with split-fp16 fp32 emulation:
//   layers/LM head (2-term):  A = Ahi+Alo (fp16), B = fp16;  C = Ahi*B + Alo*B
//   generator     (3-term):   B also split;  C = Ahi*Bhi + Ahi*Blo + Alo*Bhi
// fp32 accumulate. CTA tile 128x128, BK=32, cp.async double buffering.
// ---------------------------------------------------------------------------

#define D       1024
#define NLAYERS 8
#define VOCAB   32000
#define GH      256
#define NTOK    4096
#define NMAT    16
#define NROWS   65536
#define ENC_K   64
#define EPSV    1.1920929e-07f

typedef __half f16;

// ------------------------- scratch (device globals) ------------------------
__device__ float g_Xf[NTOK * D];                                 // fp32 residual
__device__ f16   g_Hhi[NTOK * D],  g_Hlo[NTOK * D];              // normed acts (A-split)
__device__ f16   g_W[(size_t)NMAT * D * D];                      // generated W (B, single)
__device__ f16   g_G0hi[(size_t)NROWS * GH], g_G0lo[(size_t)NROWS * GH];
__device__ f16   g_G1hi[(size_t)NROWS * GH], g_G1lo[(size_t)NROWS * GH];
__device__ f16   g_Ehi[(size_t)NROWS * ENC_K], g_Elo[(size_t)NROWS * ENC_K];
__device__ f16   g_W0Phi[GH * ENC_K], g_W0Plo[GH * ENC_K];       // generator B (split)
__device__ f16   g_W1hi[GH * GH], g_W1lo[GH * GH];
__device__ f16   g_W2hi[GH * GH], g_W2lo[GH * GH];
__device__ f16   g_W3hi[GH * GH], g_W3lo[GH * GH];
__device__ f16   g_LM[(size_t)VOCAB * D];                        // lm head B (single)

// ------------------------------- PTX helpers -------------------------------
__device__ __forceinline__ uint32_t smem_u32(const void* p) {
    uint32_t a;
    asm("{ .reg .u64 t; cvta.to.shared.u64 t, %1; cvt.u32.u64 %0, t; }"
        : "=r"(a) : "l"(p));
    return a;
}

__device__ __forceinline__ void ldmx4(uint32_t* r, uint32_t addr) {
    asm volatile("ldmatrix.sync.aligned.m8n8.x4.shared.b16 {%0,%1,%2,%3}, [%4];"
                 : "=r"(r[0]), "=r"(r[1]), "=r"(r[2]), "=r"(r[3]) : "r"(addr));
}

__device__ __forceinline__ void mma16816(float* c, const uint32_t* a,
                                         uint32_t b0, uint32_t b1) {
    asm volatile(
        "mma.sync.aligned.m16n8k16.row.col.f32.f16.f16.f32 "
        "{%0,%1,%2,%3}, {%4,%5,%6,%7}, {%8,%9}, {%0,%1,%2,%3};"
        : "+f"(c[0]), "+f"(c[1]), "+f"(c[2]), "+f"(c[3])
        : "r"(a[0]), "r"(a[1]), "r"(a[2]), "r"(a[3]), "r"(b0), "r"(b1));
}

__device__ __forceinline__ void cp16(uint32_t saddr, const void* gaddr) {
    asm volatile("cp.async.cg.shared.global [%0], [%1], 16;"
                 :: "r"(saddr), "l"(gaddr) : "memory");
}
#define CP_COMMIT() asm volatile("cp.async.commit_group;" ::: "memory")
#define CP_WAIT(N)  asm volatile("cp.async.wait_group %0;" :: "n"(N) : "memory")

// --------------------------- split/misc helpers ----------------------------
__device__ __forceinline__ void split1(float v, f16& h, f16& l) {
    h = __float2half_rn(v);
    l = __float2half_rn(v - __half2float(h));
}

__device__ __forceinline__ void store_split2(f16* ph, f16* pl,
                                             float v0, float v1) {
    f16 h0, l0, h1, l1;
    split1(v0, h0, l0); split1(v1, h1, l1);
    __half2 hh; hh.x = h0; hh.y = h1;
    __half2 ll; ll.x = l0; ll.y = l1;
    *(__half2*)ph = hh;
    *(__half2*)pl = ll;
}

__device__ __forceinline__ void store_split4(f16* ph, f16* pl,
                                             float v0, float v1, float v2, float v3) {
    store_split2(ph, pl, v0, v1);
    store_split2(ph + 2, pl + 2, v2, v3);
}

__device__ __forceinline__ float siluf(float v) {
    return v / (1.0f + __expf(-v));
}

// ------------------------------ tiny kernels -------------------------------
__global__ void k_gather(const int* __restrict__ tok,
                         const float* __restrict__ emb) {
    int t  = blockIdx.x;
    int tk = tok[t];
    const float4* src = (const float4*)(emb + (size_t)tk * D);
    float4*       dst = (float4*)(g_Xf + (size_t)t * D);
    dst[threadIdx.x] = src[threadIdx.x];
}

__global__ void k_padw0(const float* __restrict__ w0) {
    int g = blockIdx.x;
    int f = threadIdx.x;
    float v = (f < 52) ? w0[g * 52 + f] : 0.0f;
    f16 h, l; split1(v, h, l);
    g_W0Phi[g * ENC_K + f] = h;
    g_W0Plo[g * ENC_K + f] = l;
}

__global__ void k_split(const float* __restrict__ s, f16* __restrict__ hi,
                        f16* __restrict__ lo, int n) {
    int i = blockIdx.x * blockDim.x + threadIdx.x;
    if (i < n) {
        f16 h, l; split1(s[i], h, l);
        hi[i] = h; lo[i] = l;
    }
}

__global__ void k_cvt(const float* __restrict__ s, f16* __restrict__ d, int n) {
    int i = blockIdx.x * blockDim.x + threadIdx.x;
    if (i < n) d[i] = __float2half_rn(s[i]);
}

__global__ void k_encode() {
    int idx = blockIdx.x * blockDim.x + threadIdx.x;
    if (idx >= NROWS * ENC_K) return;
    int row = idx >> 6;
    int f   = idx & 63;
    float val = 0.0f;
    if (f < 52) {
        int   mat = row >> 12;
        int   blk = row & 4095;
        float c0  = (float)(mat >> 1) * (1.0f / 7.0f);
        float c1  = (float)(blk >> 6) * (1.0f / 63.0f);
        float c2  = (float)(blk & 63) * (1.0f / 63.0f);
        float c3  = (mat & 1) ? 0.5f : 0.0f;
        float coords[4] = {c0, c1, c2, c3};
        if (f < 4) {
            val = coords[f];
        } else {
            int   q = f - 4;
            int   g = q >> 3;
            int   r = q & 7;
            float a = (float)(1 << g) * 3.14159265358979f * coords[r & 3];
            val = (r >= 4) ? cosf(a) : sinf(a);
        }
    }
    f16 h, l; split1(val, h, l);
    g_Ehi[idx] = h; g_Elo[idx] = l;
}

__global__ void k_rmsnorm(const float* __restrict__ x,
                          const float* __restrict__ w,
                          f16* __restrict__ hhi, f16* __restrict__ hlo) {
    int t   = threadIdx.x;   // 256
    int row = blockIdx.x;
    const float4* xr = (const float4*)(x + (size_t)row * D);
    float4 a = xr[t];
    float  s = a.x * a.x + a.y * a.y + a.z * a.z + a.w * a.w;
    #pragma unroll
    for (int o = 16; o > 0; o >>= 1) s += __shfl_xor_sync(0xffffffffu, s, o);
    __shared__ float sm[8];
    if ((t & 31) == 0) sm[t >> 5] = s;
    __syncthreads();
    float tot = 0.0f;
    #pragma unroll
    for (int i = 0; i < 8; i++) tot += sm[i];
    float inv = rsqrtf(tot * (1.0f / 1024.0f) + EPSV);
    float4 wv = ((const float4*)w)[t];
    store_split4(hhi + (size_t)row * D + t * 4, hlo + (size_t)row * D + t * 4,
                 a.x * inv * wv.x, a.y * inv * wv.y,
                 a.z * inv * wv.z, a.w * inv * wv.w);
}

// ------------------------- HMMA split-fp16 GEMM -----------------------------
// grid.x = M/128 (fast axis -> B-tile reuse in L2), grid.y = N/128.
// 256 threads = 8 warps in 2(M) x 4(N); warp tile 64x32; BK=32, 2 stages.
// SMEM per stage: Ahi|Alo|B[hi]|(Blo if BSPLIT); 128 rows x 80B (32 f16 + pad).
enum { EPI_STORE = 0, EPI_SILU = 1, EPI_GENW = 2, EPI_RESID = 3, EPI_RESID_SILU = 4 };

#define LDB        80
#define MAT_BYTES  10240         // 128 * 80

template <int EPI, bool BSPLIT>
__global__ void __launch_bounds__(256)
k_gemm(const f16* __restrict__ Ahi, const f16* __restrict__ Alo,
       const f16* __restrict__ Bhi, const f16* __restrict__ Blo,
       const float* __restrict__ bias,
       float* __restrict__ outF,
       f16* __restrict__ outHi, f16* __restrict__ outLo,
       int M, int N, int K) {
    constexpr int NMATS = BSPLIT ? 4 : 3;
    constexpr uint32_t STAGE = NMATS * MAT_BYTES;
    extern __shared__ char smem[];
    const uint32_t sb   = smem_u32(smem);
    const int tid  = threadIdx.x;
    const int lane = tid & 31;
    const int wid  = tid >> 5;
    const int wm   = wid >> 2;          // 0..1
    const int wn   = wid & 3;           // 0..3
    const int bm   = blockIdx.x * 128;
    const int bn   = blockIdx.y * 128;

    float acc[4][4][4];
    #pragma unroll
    for (int i = 0; i < 4; i++)
        #pragma unroll
        for (int j = 0; j < 4; j++)
            #pragma unroll
            for (int q = 0; q < 4; q++) acc[i][j][q] = 0.0f;

    // ldmatrix per-lane byte offsets
    const uint32_t a_off = (uint32_t)(lane & 15) * LDB + (uint32_t)(lane >> 4) * 16;
    const uint32_t b_off = (uint32_t)((lane & 7) + ((lane >> 4) & 1) * 8) * LDB
                         + (uint32_t)((lane >> 3) & 1) * 16;

    const int nch = K >> 5;

    // ---- stage loader: (NMATS*512) x 16B cp.async ----
    auto load_stage = [&](int ic, int buf) {
        const int k0 = ic << 5;
        const uint32_t sbase = sb + buf * STAGE;
        #pragma unroll
        for (int it = 0; it < NMATS * 2; it++) {
            int u   = tid + it * 256;
            int seg = u >> 2;
            int c   = u & 3;
            const f16* src; uint32_t moff; int rl;
            if (seg < 128)      { src = Ahi + (size_t)(bm + seg) * K;       moff = 0;             rl = seg; }
            else if (seg < 256) { src = Alo + (size_t)(bm + seg - 128) * K; moff = MAT_BYTES;     rl = seg - 128; }
            else if (seg < 384) { src = Bhi + (size_t)(bn + seg - 256) * K; moff = 2 * MAT_BYTES; rl = seg - 256; }
            else                { src = Blo + (size_t)(bn + seg - 384) * K; moff = 3 * MAT_BYTES; rl = seg - 384; }
            cp16(sbase + moff + (uint32_t)rl * LDB + (uint32_t)c * 16, src + k0 + c * 8);
        }
        CP_COMMIT();
    };

    auto compute = [&](int buf) {
        const uint32_t base = sb + buf * STAGE;
        #pragma unroll
        for (int ks = 0; ks < 2; ks++) {
            uint32_t ah[4][4], al[4][4], bh[2][4], bl[2][4];
            #pragma unroll
            for (int mt = 0; mt < 4; mt++) {
                uint32_t t0 = (uint32_t)(wm * 64 + mt * 16) * LDB + (uint32_t)ks * 32;
                ldmx4(ah[mt], base + t0 + a_off);
                ldmx4(al[mt], base + MAT_BYTES + t0 + a_off);
            }
            #pragma unroll
            for (int g = 0; g < 2; g++) {
                uint32_t t0 = (uint32_t)(wn * 32 + g * 16) * LDB + (uint32_t)ks * 32;
                ldmx4(bh[g], base + 2 * MAT_BYTES + t0 + b_off);
                if (BSPLIT) ldmx4(bl[g], base + 3 * MAT_BYTES + t0 + b_off);
            }
            #pragma unroll
            for (int mt = 0; mt < 4; mt++)
                #pragma unroll
                for (int nt = 0; nt < 4; nt++) {
                    const int g = nt >> 1, h = (nt & 1) * 2;
                    mma16816(acc[mt][nt], ah[mt], bh[g][h], bh[g][h + 1]);
                    if (BSPLIT)
                        mma16816(acc[mt][nt], ah[mt], bl[g][h], bl[g][h + 1]);
                    mma16816(acc[mt][nt], al[mt], bh[g][h], bh[g][h + 1]);
                }
        }
    };

    // ---- pipelined main loop ----
    load_stage(0, 0);
    if (nch > 1) load_stage(1, 1);
    for (int ic = 0; ic < nch; ic++) {
        if (ic + 1 < nch) { CP_WAIT(1); } else { CP_WAIT(0); }
        __syncthreads();
        compute(ic & 1);
        __syncthreads();
        if (ic + 2 < nch) load_stage(ic + 2, ic & 1);
    }

    // ------------------------------ epilogue --------------------------------
    #pragma unroll
    for (int mt = 0; mt < 4; mt++) {
        #pragma unroll
        for (int nt = 0; nt < 4; nt++) {
            const int n0 = bn + wn * 32 + nt * 8 + (lane & 3) * 2;
            #pragma unroll
            for (int half_ = 0; half_ < 2; half_++) {
                const int m = bm + wm * 64 + mt * 16 + (lane >> 2) + half_ * 8;
                float v0 = acc[mt][nt][half_ * 2 + 0];
                float v1 = acc[mt][nt][half_ * 2 + 1];
                if (EPI == EPI_STORE) {
                    *(float2*)&outF[(size_t)m * N + n0] = make_float2(v0, v1);
                } else if (EPI == EPI_SILU) {
                    const float2 bb = *(const float2*)&bias[n0];
                    store_split2(outHi + (size_t)m * N + n0,
                                 outLo + (size_t)m * N + n0,
                                 siluf(v0 + bb.x), siluf(v1 + bb.y));
                } else if (EPI == EPI_GENW) {
                    const float2 bb = *(const float2*)&bias[n0];
                    int mat = m >> 12, rb_ = (m >> 6) & 63, cb_ = m & 63;
                    int ii = n0 >> 4, jj = n0 & 15;  // pair stays in 16-block
                    size_t off = (size_t)mat * D * D + (size_t)(rb_ * 16 + ii) * D
                               + (size_t)(cb_ * 16 + jj);
                    __half2 wv;
                    wv.x = __float2half_rn(v0 + bb.x);
                    wv.y = __float2half_rn(v1 + bb.y);
                    *(__half2*)&outHi[off] = wv;
                } else if (EPI == EPI_RESID) {
                    float2* p = (float2*)&outF[(size_t)m * N + n0];
                    float2 c = *p;
                    *p = make_float2(c.x + 0.1f * v0, c.y + 0.1f * v1);
                } else { // EPI_RESID_SILU
                    float2* p = (float2*)&outF[(size_t)m * N + n0];
                    float2 c = *p;
                    *p = make_float2(c.x + 0.1f * siluf(v0), c.y + 0.1f * siluf(v1));
                }
            }
        }
    }
}

// --------------------------------- driver -----------------------------------
extern "C" void kernel_launch(void* const* d_in, const int* in_sizes, int n_in,
                              void* d_out, int out_size) {
    const int*   tokens = (const int*)d_in[0];
    const float* embed  = (const float*)d_in[1];
    const float* lmhead = (const float*)d_in[2];
    const float* finw   = (const float*)d_in[3];
    const float* n1w    = (const float*)d_in[4];
    const float* n2w    = (const float*)d_in[5];
    const float* w0     = (const float*)d_in[6];
    const float* b0     = (const float*)d_in[7];
    const float* w1     = (const float*)d_in[8];
    const float* b1     = (const float*)d_in[9];
    const float* w2     = (const float*)d_in[10];
    const float* b2     = (const float*)d_in[11];
    const float* w3     = (const float*)d_in[12];
    const float* b3     = (const float*)d_in[13];
    float* out = (float*)d_out;

    float *pXf;
    f16 *pHhi, *pHlo, *pW, *pG0hi, *pG0lo, *pG1hi, *pG1lo;
    f16 *pEhi, *pElo, *pW0Phi, *pW0Plo;
    f16 *pW1hi, *pW1lo, *pW2hi, *pW2lo, *pW3hi, *pW3lo, *pLM;
    cudaGetSymbolAddress((void**)&pXf,    g_Xf);
    cudaGetSymbolAddress((void**)&pHhi,   g_Hhi);
    cudaGetSymbolAddress((void**)&pHlo,   g_Hlo);
    cudaGetSymbolAddress((void**)&pW,     g_W);
    cudaGetSymbolAddress((void**)&pG0hi,  g_G0hi);
    cudaGetSymbolAddress((void**)&pG0lo,  g_G0lo);
    cudaGetSymbolAddress((void**)&pG1hi,  g_G1hi);
    cudaGetSymbolAddress((void**)&pG1lo,  g_G1lo);
    cudaGetSymbolAddress((void**)&pEhi,   g_Ehi);
    cudaGetSymbolAddress((void**)&pElo,   g_Elo);
    cudaGetSymbolAddress((void**)&pW0Phi, g_W0Phi);
    cudaGetSymbolAddress((void**)&pW0Plo, g_W0Plo);
    cudaGetSymbolAddress((void**)&pW1hi,  g_W1hi);
    cudaGetSymbolAddress((void**)&pW1lo,  g_W1lo);
    cudaGetSymbolAddress((void**)&pW2hi,  g_W2hi);
    cudaGetSymbolAddress((void**)&pW2lo,  g_W2lo);
    cudaGetSymbolAddress((void**)&pW3hi,  g_W3hi);
    cudaGetSymbolAddress((void**)&pW3lo,  g_W3lo);
    cudaGetSymbolAddress((void**)&pLM,    g_LM);

    const int SM3 = 2 * 3 * MAT_BYTES;   // 61440
    const int SM4 = 2 * 4 * MAT_BYTES;   // 81920
    cudaFuncSetAttribute(k_gemm<EPI_STORE, false>,      cudaFuncAttributeMaxDynamicSharedMemorySize, SM3);
    cudaFuncSetAttribute(k_gemm<EPI_RESID, false>,      cudaFuncAttributeMaxDynamicSharedMemorySize, SM3);
    cudaFuncSetAttribute(k_gemm<EPI_RESID_SILU, false>, cudaFuncAttributeMaxDynamicSharedMemorySize, SM3);
    cudaFuncSetAttribute(k_gemm<EPI_SILU, true>,        cudaFuncAttributeMaxDynamicSharedMemorySize, SM4);
    cudaFuncSetAttribute(k_gemm<EPI_GENW, true>,        cudaFuncAttributeMaxDynamicSharedMemorySize, SM4);

    // --- inputs -> fp16 (splits), embed gather, coord encoding ---
    k_gather<<<NTOK, 256>>>(tokens, embed);
    k_padw0<<<GH, ENC_K>>>(w0);
    k_encode<<<(NROWS * ENC_K + 255) / 256, 256>>>();
    k_split<<<(GH * GH + 255) / 256, 256>>>(w1, pW1hi, pW1lo, GH * GH);
    k_split<<<(GH * GH + 255) / 256, 256>>>(w2, pW2hi, pW2lo, GH * GH);
    k_split<<<(GH * GH + 255) / 256, 256>>>(w3, pW3hi, pW3lo, GH * GH);
    k_cvt<<<(VOCAB * D + 255) / 256, 256>>>(lmhead, pLM, VOCAB * D);

    // --- generate all 16 weight matrices (batched coord-MLP, 3-term) ---
    dim3 gg(NROWS / 128, GH / 128);   // (512, 2)
    k_gemm<EPI_SILU, true><<<gg, 256, SM4>>>(pEhi, pElo, pW0Phi, pW0Plo, b0,
                                             nullptr, pG0hi, pG0lo, NROWS, GH, ENC_K);
    k_gemm<EPI_SILU, true><<<gg, 256, SM4>>>(pG0hi, pG0lo, pW1hi, pW1lo, b1,
                                             nullptr, pG1hi, pG1lo, NROWS, GH, GH);
    k_gemm<EPI_SILU, true><<<gg, 256, SM4>>>(pG1hi, pG1lo, pW2hi, pW2lo, b2,
                                             nullptr, pG0hi, pG0lo, NROWS, GH, GH);
    k_gemm<EPI_GENW, true><<<gg, 256, SM4>>>(pG0hi, pG0lo, pW3hi, pW3lo, b3,
                                             nullptr, pW, nullptr, NROWS, GH, GH);

    // --- 8 transformer layers (2-term) ---
    dim3 gl(NTOK / 128, D / 128);     // (32, 8)
    for (int li = 0; li < NLAYERS; li++) {
        k_rmsnorm<<<NTOK, 256>>>(pXf, n1w + (size_t)li * D, pHhi, pHlo);
        k_gemm<EPI_RESID, false><<<gl, 256, SM3>>>(
            pHhi, pHlo, pW + (size_t)(2 * li) * D * D, nullptr, nullptr,
            pXf, nullptr, nullptr, NTOK, D, D);
        k_rmsnorm<<<NTOK, 256>>>(pXf, n2w + (size_t)li * D, pHhi, pHlo);
        k_gemm<EPI_RESID_SILU, false><<<gl, 256, SM3>>>(
            pHhi, pHlo, pW + (size_t)(2 * li + 1) * D * D, nullptr, nullptr,
            pXf, nullptr, nullptr, NTOK, D, D);
    }

    // --- final norm + LM head (2-term) ---
    k_rmsnorm<<<NTOK, 256>>>(pXf, finw, pHhi, pHlo);
    dim3 gf(NTOK / 128, VOCAB / 128); // (32, 250)
    k_gemm<EPI_STORE, false><<<gf, 256, SM3>>>(
        pHhi, pHlo, pLM, nullptr, nullptr, out, nullptr, nullptr,
        NTOK, VOCAB, D);
}

// round 16
// speedup vs baseline: 4.9985x; 1.4764x over previous
#include <cuda_runtime.h>
#include <cuda_fp16.h>
#include <math.h>
#include <stdint.h>

// ---------------------------------------------------------------------------
// GWEModel on tensor cores (HMMA mma.sync m16n8k16 fp16, fp32 accumulate).
// GEMMs are C[M,N] = A[M,K] @ B[N,K]^T:
//   generator MLP (3-term split): A=Ahi+Alo, B=Bhi+Blo; C = AhBh + AhBl + AlBh
//   layers / LM head (1-term):    plain fp16 A and B
// CTA tile 128x128, BK=32, cp.async double buffering.
// ---------------------------------------------------------------------------

#define D       1024
#define NLAYERS 8
#define VOCAB   32000
#define GH      256
#define NTOK    4096
#define NMAT    16
#define NROWS   65536
#define ENC_K   64
#define EPSV    1.1920929e-07f

typedef __half f16;

// ------------------------- scratch (device globals) ------------------------
__device__ float g_Xf[NTOK * D];                                 // fp32 residual
__device__ f16   g_H[NTOK * D];                                  // normed acts (fp16)
__device__ f16   g_W[(size_t)NMAT * D * D];                      // generated W (fp16)
__device__ f16   g_G0hi[(size_t)NROWS * GH], g_G0lo[(size_t)NROWS * GH];
__device__ f16   g_G1hi[(size_t)NROWS * GH], g_G1lo[(size_t)NROWS * GH];
__device__ f16   g_Ehi[(size_t)NROWS * ENC_K], g_Elo[(size_t)NROWS * ENC_K];
__device__ f16   g_W0Phi[GH * ENC_K], g_W0Plo[GH * ENC_K];
__device__ f16   g_W1hi[GH * GH], g_W1lo[GH * GH];
__device__ f16   g_W2hi[GH * GH], g_W2lo[GH * GH];
__device__ f16   g_W3hi[GH * GH], g_W3lo[GH * GH];
__device__ f16   g_LM[(size_t)VOCAB * D];                        // lm head (fp16)

// ------------------------------- PTX helpers -------------------------------
__device__ __forceinline__ uint32_t smem_u32(const void* p) {
    uint32_t a;
    asm("{ .reg .u64 t; cvta.to.shared.u64 t, %1; cvt.u32.u64 %0, t; }"
        : "=r"(a) : "l"(p));
    return a;
}

__device__ __forceinline__ void ldmx4(uint32_t* r, uint32_t addr) {
    asm volatile("ldmatrix.sync.aligned.m8n8.x4.shared.b16 {%0,%1,%2,%3}, [%4];"
                 : "=r"(r[0]), "=r"(r[1]), "=r"(r[2]), "=r"(r[3]) : "r"(addr));
}

__device__ __forceinline__ void mma16816(float* c, const uint32_t* a,
                                         uint32_t b0, uint32_t b1) {
    asm volatile(
        "mma.sync.aligned.m16n8k16.row.col.f32.f16.f16.f32 "
        "{%0,%1,%2,%3}, {%4,%5,%6,%7}, {%8,%9}, {%0,%1,%2,%3};"
        : "+f"(c[0]), "+f"(c[1]), "+f"(c[2]), "+f"(c[3])
        : "r"(a[0]), "r"(a[1]), "r"(a[2]), "r"(a[3]), "r"(b0), "r"(b1));
}

__device__ __forceinline__ void cp16(uint32_t saddr, const void* gaddr) {
    asm volatile("cp.async.cg.shared.global [%0], [%1], 16;"
                 :: "r"(saddr), "l"(gaddr) : "memory");
}
#define CP_COMMIT() asm volatile("cp.async.commit_group;" ::: "memory")
#define CP_WAIT(N)  asm volatile("cp.async.wait_group %0;" :: "n"(N) : "memory")

// --------------------------- split/misc helpers ----------------------------
__device__ __forceinline__ void split1(float v, f16& h, f16& l) {
    h = __float2half_rn(v);
    l = __float2half_rn(v - __half2float(h));
}

__device__ __forceinline__ void store_split2(f16* ph, f16* pl,
                                             float v0, float v1) {
    f16 h0, l0, h1, l1;
    split1(v0, h0, l0); split1(v1, h1, l1);
    __half2 hh; hh.x = h0; hh.y = h1;
    __half2 ll; ll.x = l0; ll.y = l1;
    *(__half2*)ph = hh;
    *(__half2*)pl = ll;
}

__device__ __forceinline__ float siluf(float v) {
    return v / (1.0f + __expf(-v));
}

// ------------------------------ tiny kernels -------------------------------
__global__ void k_gather(const int* __restrict__ tok,
                         const float* __restrict__ emb) {
    int t  = blockIdx.x;
    int tk = tok[t];
    const float4* src = (const float4*)(emb + (size_t)tk * D);
    float4*       dst = (float4*)(g_Xf + (size_t)t * D);
    dst[threadIdx.x] = src[threadIdx.x];
}

__global__ void k_padw0(const float* __restrict__ w0) {
    int g = blockIdx.x;
    int f = threadIdx.x;
    float v = (f < 52) ? w0[g * 52 + f] : 0.0f;
    f16 h, l; split1(v, h, l);
    g_W0Phi[g * ENC_K + f] = h;
    g_W0Plo[g * ENC_K + f] = l;
}

__global__ void k_split(const float* __restrict__ s, f16* __restrict__ hi,
                        f16* __restrict__ lo, int n) {
    int i = blockIdx.x * blockDim.x + threadIdx.x;
    if (i < n) {
        f16 h, l; split1(s[i], h, l);
        hi[i] = h; lo[i] = l;
    }
}

__global__ void k_cvt(const float* __restrict__ s, f16* __restrict__ d, int n) {
    int i = blockIdx.x * blockDim.x + threadIdx.x;
    if (i < n) d[i] = __float2half_rn(s[i]);
}

__global__ void k_encode() {
    int idx = blockIdx.x * blockDim.x + threadIdx.x;
    if (idx >= NROWS * ENC_K) return;
    int row = idx >> 6;
    int f   = idx & 63;
    float val = 0.0f;
    if (f < 52) {
        int   mat = row >> 12;
        int   blk = row & 4095;
        float c0  = (float)(mat >> 1) * (1.0f / 7.0f);
        float c1  = (float)(blk >> 6) * (1.0f / 63.0f);
        float c2  = (float)(blk & 63) * (1.0f / 63.0f);
        float c3  = (mat & 1) ? 0.5f : 0.0f;
        float coords[4] = {c0, c1, c2, c3};
        if (f < 4) {
            val = coords[f];
        } else {
            int   q = f - 4;
            int   g = q >> 3;
            int   r = q & 7;
            float a = (float)(1 << g) * 3.14159265358979f * coords[r & 3];
            val = (r >= 4) ? cosf(a) : sinf(a);
        }
    }
    f16 h, l; split1(val, h, l);
    g_Ehi[idx] = h; g_Elo[idx] = l;
}

__global__ void k_rmsnorm(const float* __restrict__ x,
                          const float* __restrict__ w,
                          f16* __restrict__ h) {
    int t   = threadIdx.x;   // 256
    int row = blockIdx.x;
    const float4* xr = (const float4*)(x + (size_t)row * D);
    float4 a = xr[t];
    float  s = a.x * a.x + a.y * a.y + a.z * a.z + a.w * a.w;
    #pragma unroll
    for (int o = 16; o > 0; o >>= 1) s += __shfl_xor_sync(0xffffffffu, s, o);
    __shared__ float sm[8];
    if ((t & 31) == 0) sm[t >> 5] = s;
    __syncthreads();
    float tot = 0.0f;
    #pragma unroll
    for (int i = 0; i < 8; i++) tot += sm[i];
    float inv = rsqrtf(tot * (1.0f / 1024.0f) + EPSV);
    float4 wv = ((const float4*)w)[t];
    __half2 o0, o1;
    o0.x = __float2half_rn(a.x * inv * wv.x);
    o0.y = __float2half_rn(a.y * inv * wv.y);
    o1.x = __float2half_rn(a.z * inv * wv.z);
    o1.y = __float2half_rn(a.w * inv * wv.w);
    *(__half2*)(h + (size_t)row * D + t * 4)     = o0;
    *(__half2*)(h + (size_t)row * D + t * 4 + 2) = o1;
}

// ------------------------- HMMA split-fp16 GEMM -----------------------------
// grid.x = M/128 (fast axis -> B-tile reuse in L2), grid.y = N/128.
// 256 threads = 8 warps in 2(M) x 4(N); warp tile 64x32; BK=32, 2 stages.
// SMEM per stage: A0 [A1] B0 [B1]; each 128 rows x 80B (32 f16 + pad).
enum { EPI_STORE = 0, EPI_SILU = 1, EPI_GENW = 2, EPI_RESID = 3, EPI_RESID_SILU = 4 };

#define LDB        80
#define MAT_BYTES  10240         // 128 * 80

template <int EPI, bool ASPLIT, bool BSPLIT>
__global__ void __launch_bounds__(256)
k_gemm(const f16* __restrict__ Ahi, const f16* __restrict__ Alo,
       const f16* __restrict__ Bhi, const f16* __restrict__ Blo,
       const float* __restrict__ bias,
       float* __restrict__ outF,
       f16* __restrict__ outHi, f16* __restrict__ outLo,
       int M, int N, int K) {
    constexpr int NA    = ASPLIT ? 2 : 1;
    constexpr int NMATS = NA + (BSPLIT ? 2 : 1);
    constexpr uint32_t BOFF  = (uint32_t)NA * MAT_BYTES;
    constexpr uint32_t STAGE = (uint32_t)NMATS * MAT_BYTES;
    extern __shared__ char smem[];
    const uint32_t sb   = smem_u32(smem);
    const int tid  = threadIdx.x;
    const int lane = tid & 31;
    const int wid  = tid >> 5;
    const int wm   = wid >> 2;          // 0..1
    const int wn   = wid & 3;           // 0..3
    const int bm   = blockIdx.x * 128;
    const int bn   = blockIdx.y * 128;

    float acc[4][4][4];
    #pragma unroll
    for (int i = 0; i < 4; i++)
        #pragma unroll
        for (int j = 0; j < 4; j++)
            #pragma unroll
            for (int q = 0; q < 4; q++) acc[i][j][q] = 0.0f;

    // ldmatrix per-lane byte offsets
    const uint32_t a_off = (uint32_t)(lane & 15) * LDB + (uint32_t)(lane >> 4) * 16;
    const uint32_t b_off = (uint32_t)((lane & 7) + ((lane >> 4) & 1) * 8) * LDB
                         + (uint32_t)((lane >> 3) & 1) * 16;

    const int nch = K >> 5;

    // ---- stage loader: (NMATS*512) x 16B cp.async ----
    auto load_stage = [&](int ic, int buf) {
        const int k0 = ic << 5;
        const uint32_t sbase = sb + buf * STAGE;
        #pragma unroll
        for (int it = 0; it < NMATS * 2; it++) {
            int u   = tid + it * 256;
            int seg = u >> 2;            // 0 .. NMATS*128-1
            int c   = u & 3;
            int mat = seg >> 7;
            int rl  = seg & 127;
            const f16* src;
            if (mat == 0)            src = Ahi + (size_t)(bm + rl) * K;
            else if (ASPLIT && mat == 1) src = Alo + (size_t)(bm + rl) * K;
            else if (mat == NA)      src = Bhi + (size_t)(bn + rl) * K;
            else                     src = Blo + (size_t)(bn + rl) * K;
            cp16(sbase + (uint32_t)mat * MAT_BYTES + (uint32_t)rl * LDB
                 + (uint32_t)c * 16, src + k0 + c * 8);
        }
        CP_COMMIT();
    };

    auto compute = [&](int buf) {
        const uint32_t base = sb + buf * STAGE;
        #pragma unroll
        for (int ks = 0; ks < 2; ks++) {
            uint32_t ah[4][4], al[4][4], bh[2][4], bl[2][4];
            #pragma unroll
            for (int mt = 0; mt < 4; mt++) {
                uint32_t t0 = (uint32_t)(wm * 64 + mt * 16) * LDB + (uint32_t)ks * 32;
                ldmx4(ah[mt], base + t0 + a_off);
                if (ASPLIT) ldmx4(al[mt], base + MAT_BYTES + t0 + a_off);
            }
            #pragma unroll
            for (int g = 0; g < 2; g++) {
                uint32_t t0 = (uint32_t)(wn * 32 + g * 16) * LDB + (uint32_t)ks * 32;
                ldmx4(bh[g], base + BOFF + t0 + b_off);
                if (BSPLIT) ldmx4(bl[g], base + BOFF + MAT_BYTES + t0 + b_off);
            }
            #pragma unroll
            for (int mt = 0; mt < 4; mt++)
                #pragma unroll
                for (int nt = 0; nt < 4; nt++) {
                    const int g = nt >> 1, h = (nt & 1) * 2;
                    mma16816(acc[mt][nt], ah[mt], bh[g][h], bh[g][h + 1]);
                    if (BSPLIT)
                        mma16816(acc[mt][nt], ah[mt], bl[g][h], bl[g][h + 1]);
                    if (ASPLIT)
                        mma16816(acc[mt][nt], al[mt], bh[g][h], bh[g][h + 1]);
                }
        }
    };

    // ---- pipelined main loop ----
    load_stage(0, 0);
    if (nch > 1) load_stage(1, 1);
    for (int ic = 0; ic < nch; ic++) {
        if (ic + 1 < nch) { CP_WAIT(1); } else { CP_WAIT(0); }
        __syncthreads();
        compute(ic & 1);
        __syncthreads();
        if (ic + 2 < nch) load_stage(ic + 2, ic & 1);
    }

    // ------------------------------ epilogue --------------------------------
    #pragma unroll
    for (int mt = 0; mt < 4; mt++) {
        #pragma unroll
        for (int nt = 0; nt < 4; nt++) {
            const int n0 = bn + wn * 32 + nt * 8 + (lane & 3) * 2;
            #pragma unroll
            for (int half_ = 0; half_ < 2; half_++) {
                const int m = bm + wm * 64 + mt * 16 + (lane >> 2) + half_ * 8;
                float v0 = acc[mt][nt][half_ * 2 + 0];
                float v1 = acc[mt][nt][half_ * 2 + 1];
                if (EPI == EPI_STORE) {
                    *(float2*)&outF[(size_t)m * N + n0] = make_float2(v0, v1);
                } else if (EPI == EPI_SILU) {
                    const float2 bb = *(const float2*)&bias[n0];
                    store_split2(outHi + (size_t)m * N + n0,
                                 outLo + (size_t)m * N + n0,
                                 siluf(v0 + bb.x), siluf(v1 + bb.y));
                } else if (EPI == EPI_GENW) {
                    const float2 bb = *(const float2*)&bias[n0];
                    int mat = m >> 12, rb_ = (m >> 6) & 63, cb_ = m & 63;
                    int ii = n0 >> 4, jj = n0 & 15;  // pair stays in 16-block
                    size_t off = (size_t)mat * D * D + (size_t)(rb_ * 16 + ii) * D
                               + (size_t)(cb_ * 16 + jj);
                    __half2 wv;
                    wv.x = __float2half_rn(v0 + bb.x);
                    wv.y = __float2half_rn(v1 + bb.y);
                    *(__half2*)&outHi[off] = wv;
                } else if (EPI == EPI_RESID) {
                    float2* p = (float2*)&outF[(size_t)m * N + n0];
                    float2 c = *p;
                    *p = make_float2(c.x + 0.1f * v0, c.y + 0.1f * v1);
                } else { // EPI_RESID_SILU
                    float2* p = (float2*)&outF[(size_t)m * N + n0];
                    float2 c = *p;
                    *p = make_float2(c.x + 0.1f * siluf(v0), c.y + 0.1f * siluf(v1));
                }
            }
        }
    }
}

// --------------------------------- driver -----------------------------------
extern "C" void kernel_launch(void* const* d_in, const int* in_sizes, int n_in,
                              void* d_out, int out_size) {
    const int*   tokens = (const int*)d_in[0];
    const float* embed  = (const float*)d_in[1];
    const float* lmhead = (const float*)d_in[2];
    const float* finw   = (const float*)d_in[3];
    const float* n1w    = (const float*)d_in[4];
    const float* n2w    = (const float*)d_in[5];
    const float* w0     = (const float*)d_in[6];
    const float* b0     = (const float*)d_in[7];
    const float* w1     = (const float*)d_in[8];
    const float* b1     = (const float*)d_in[9];
    const float* w2     = (const float*)d_in[10];
    const float* b2     = (const float*)d_in[11];
    const float* w3     = (const float*)d_in[12];
    const float* b3     = (const float*)d_in[13];
    float* out = (float*)d_out;

    float *pXf;
    f16 *pH, *pW, *pG0hi, *pG0lo, *pG1hi, *pG1lo;
    f16 *pEhi, *pElo, *pW0Phi, *pW0Plo;
    f16 *pW1hi, *pW1lo, *pW2hi, *pW2lo, *pW3hi, *pW3lo, *pLM;
    cudaGetSymbolAddress((void**)&pXf,    g_Xf);
    cudaGetSymbolAddress((void**)&pH,     g_H);
    cudaGetSymbolAddress((void**)&pW,     g_W);
    cudaGetSymbolAddress((void**)&pG0hi,  g_G0hi);
    cudaGetSymbolAddress((void**)&pG0lo,  g_G0lo);
    cudaGetSymbolAddress((void**)&pG1hi,  g_G1hi);
    cudaGetSymbolAddress((void**)&pG1lo,  g_G1lo);
    cudaGetSymbolAddress((void**)&pEhi,   g_Ehi);
    cudaGetSymbolAddress((void**)&pElo,   g_Elo);
    cudaGetSymbolAddress((void**)&pW0Phi, g_W0Phi);
    cudaGetSymbolAddress((void**)&pW0Plo, g_W0Plo);
    cudaGetSymbolAddress((void**)&pW1hi,  g_W1hi);
    cudaGetSymbolAddress((void**)&pW1lo,  g_W1lo);
    cudaGetSymbolAddress((void**)&pW2hi,  g_W2hi);
    cudaGetSymbolAddress((void**)&pW2lo,  g_W2lo);
    cudaGetSymbolAddress((void**)&pW3hi,  g_W3hi);
    cudaGetSymbolAddress((void**)&pW3lo,  g_W3lo);
    cudaGetSymbolAddress((void**)&pLM,    g_LM);

    const int SM2 = 2 * 2 * MAT_BYTES;   // 40960  (1-term)
    const int SM4 = 2 * 4 * MAT_BYTES;   // 81920  (3-term)
    cudaFuncSetAttribute((const void*)k_gemm<EPI_STORE, false, false>,      cudaFuncAttributeMaxDynamicSharedMemorySize, SM2);
    cudaFuncSetAttribute((const void*)k_gemm<EPI_RESID, false, false>,      cudaFuncAttributeMaxDynamicSharedMemorySize, SM2);
    cudaFuncSetAttribute((const void*)k_gemm<EPI_RESID_SILU, false, false>, cudaFuncAttributeMaxDynamicSharedMemorySize, SM2);
    cudaFuncSetAttribute((const void*)k_gemm<EPI_SILU, true, true>,         cudaFuncAttributeMaxDynamicSharedMemorySize, SM4);
    cudaFuncSetAttribute((const void*)k_gemm<EPI_GENW, true, true>,         cudaFuncAttributeMaxDynamicSharedMemorySize, SM4);

    // --- inputs -> fp16 (splits), embed gather, coord encoding ---
    k_gather<<<NTOK, 256>>>(tokens, embed);
    k_padw0<<<GH, ENC_K>>>(w0);
    k_encode<<<(NROWS * ENC_K + 255) / 256, 256>>>();
    k_split<<<(GH * GH + 255) / 256, 256>>>(w1, pW1hi, pW1lo, GH * GH);
    k_split<<<(GH * GH + 255) / 256, 256>>>(w2, pW2hi, pW2lo, GH * GH);
    k_split<<<(GH * GH + 255) / 256, 256>>>(w3, pW3hi, pW3lo, GH * GH);
    k_cvt<<<(VOCAB * D + 255) / 256, 256>>>(lmhead, pLM, VOCAB * D);

    // --- generate all 16 weight matrices (batched coord-MLP, 3-term) ---
    dim3 gg(NROWS / 128, GH / 128);   // (512, 2)
    k_gemm<EPI_SILU, true, true><<<gg, 256, SM4>>>(
        pEhi, pElo, pW0Phi, pW0Plo, b0, nullptr, pG0hi, pG0lo, NROWS, GH, ENC_K);
    k_gemm<EPI_SILU, true, true><<<gg, 256, SM4>>>(
        pG0hi, pG0lo, pW1hi, pW1lo, b1, nullptr, pG1hi, pG1lo, NROWS, GH, GH);
    k_gemm<EPI_SILU, true, true><<<gg, 256, SM4>>>(
        pG1hi, pG1lo, pW2hi, pW2lo, b2, nullptr, pG0hi, pG0lo, NROWS, GH, GH);
    k_gemm<EPI_GENW, true, true><<<gg, 256, SM4>>>(
        pG0hi, pG0lo, pW3hi, pW3lo, b3, nullptr, pW, nullptr, NROWS, GH, GH);

    // --- 8 transformer layers (1-term fp16) ---
    dim3 gl(NTOK / 128, D / 128);     // (32, 8)
    for (int li = 0; li < NLAYERS; li++) {
        k_rmsnorm<<<NTOK, 256>>>(pXf, n1w + (size_t)li * D, pH);
        k_gemm<EPI_RESID, false, false><<<gl, 256, SM2>>>(
            pH, nullptr, pW + (size_t)(2 * li) * D * D, nullptr, nullptr,
            pXf, nullptr, nullptr, NTOK, D, D);
        k_rmsnorm<<<NTOK, 256>>>(pXf, n2w + (size_t)li * D, pH);
        k_gemm<EPI_RESID_SILU, false, false><<<gl, 256, SM2>>>(
            pH, nullptr, pW + (size_t)(2 * li + 1) * D * D, nullptr, nullptr,
            pXf, nullptr, nullptr, NTOK, D, D);
    }

    // --- final norm + LM head (1-term fp16) ---
    k_rmsnorm<<<NTOK, 256>>>(pXf, finw, pH);
    dim3 gf(NTOK / 128, VOCAB / 128); // (32, 250)
    k_gemm<EPI_STORE, false, false><<<gf, 256, SM2>>>(
        pH, nullptr, pLM, nullptr, nullptr, out, nullptr, nullptr,
        NTOK, VOCAB, D);
}